// round 10
// baseline (speedup 1.0000x reference)
// FlashSparseAttention — round 9: 16-warp GEMMs + register-Q flash attention.
// B=2, S=2048, H=2048, NH=16, NKV=4, HD=128, GQA groups=4, RoPE theta=1e4.
#include <cuda_runtime.h>
#include <cuda_bf16.h>
#include <math.h>
#include <stdint.h>

#define B_    2
#define S_    2048
#define H_    2048
#define NH_   16
#define NKV_  4
#define HD_   128
#define M_    (B_*S_)      // 4096 rows

// ---------------- scratch (device globals: allocation-free) ----------------
__device__ float g_cos[S_*64];
__device__ float g_sin[S_*64];

__device__ __align__(16) __nv_bfloat16 g_ah [(size_t)M_*H_],   g_al [(size_t)M_*H_];
__device__ __align__(16) __nv_bfloat16 g_wqh[(size_t)2048*H_], g_wql[(size_t)2048*H_];
__device__ __align__(16) __nv_bfloat16 g_wkh[(size_t)512*H_],  g_wkl[(size_t)512*H_];
__device__ __align__(16) __nv_bfloat16 g_wvh[(size_t)512*H_],  g_wvl[(size_t)512*H_];
__device__ __align__(16) __nv_bfloat16 g_woh[(size_t)2048*H_], g_wol[(size_t)2048*H_];
__device__ __align__(16) __nv_bfloat16 g_aoh[(size_t)M_*2048], g_aol[(size_t)M_*2048];
__device__ __align__(16) __nv_bfloat16 g_qh [(size_t)M_*NH_*HD_],  g_ql [(size_t)M_*NH_*HD_];
__device__ __align__(16) __nv_bfloat16 g_kh [(size_t)M_*NKV_*HD_], g_kl [(size_t)M_*NKV_*HD_];
__device__ __align__(16) __nv_bfloat16 g_vth[(size_t)M_*NKV_*HD_], g_vtl[(size_t)M_*NKV_*HD_];

// ---------------- PTX helpers ------------------------------------------------
__device__ __forceinline__ uint32_t smem_u32(const void* p) {
    uint32_t a;
    asm("{ .reg .u64 t; cvta.to.shared.u64 t, %1; cvt.u32.u64 %0, t; }" : "=r"(a) : "l"(p));
    return a;
}
#define CP_ASYNC16(dst, src) \
    asm volatile("cp.async.cg.shared.global [%0], [%1], 16;" :: "r"(dst), "l"(src) : "memory")
#define CP_COMMIT()  asm volatile("cp.async.commit_group;" ::: "memory")
#define CP_WAIT0()   asm volatile("cp.async.wait_group 0;" ::: "memory")
#define CP_WAIT1()   asm volatile("cp.async.wait_group 1;" ::: "memory")
#define CP_WAIT2()   asm volatile("cp.async.wait_group 2;" ::: "memory")

#define LDSM_X4(r0, r1, r2, r3, addr) \
    asm volatile("ldmatrix.sync.aligned.m8n8.x4.shared.b16 {%0,%1,%2,%3}, [%4];" \
        : "=r"(r0), "=r"(r1), "=r"(r2), "=r"(r3) : "r"(addr))

#define MMA_BF16(d, a, b0, b1) \
    asm volatile("mma.sync.aligned.m16n8k16.row.col.f32.bf16.bf16.f32 " \
        "{%0,%1,%2,%3}, {%4,%5,%6,%7}, {%8,%9}, {%0,%1,%2,%3};" \
        : "+f"((d)[0]), "+f"((d)[1]), "+f"((d)[2]), "+f"((d)[3]) \
        : "r"((a)[0]), "r"((a)[1]), "r"((a)[2]), "r"((a)[3]), "r"(b0), "r"(b1))

__device__ __forceinline__ uint32_t sw_off(int row, int chunk) {
    return (uint32_t)(row * 64 + ((chunk ^ ((row >> 1) & 3)) << 4));
}
__device__ __forceinline__ void split_pack(float x0, float x1, uint32_t& h, uint32_t& l) {
    __nv_bfloat16 h0 = __float2bfloat16(x0), h1 = __float2bfloat16(x1);
    __nv_bfloat162 hh; hh.x = h0; hh.y = h1; h = *(uint32_t*)&hh;
    __nv_bfloat162 ll;
    ll.x = __float2bfloat16(x0 - __bfloat162float(h0));
    ll.y = __float2bfloat16(x1 - __bfloat162float(h1));
    l = *(uint32_t*)&ll;
}
__device__ __forceinline__ void store_split2(__nv_bfloat16* hp, __nv_bfloat16* lp,
                                             float a, float b) {
    __nv_bfloat16 ha = __float2bfloat16(a), hb = __float2bfloat16(b);
    __nv_bfloat162 hh; hh.x = ha; hh.y = hb; *(__nv_bfloat162*)hp = hh;
    __nv_bfloat162 ll;
    ll.x = __float2bfloat16(a - __bfloat162float(ha));
    ll.y = __float2bfloat16(b - __bfloat162float(hb));
    *(__nv_bfloat162*)lp = ll;
}

// ---------------- merged bf16 split for all 5 inputs --------------------------
#define SPLIT_TOTAL 18874368
__global__ void split_all(const float* __restrict__ hs, const float* __restrict__ Wq,
                          const float* __restrict__ Wk, const float* __restrict__ Wv,
                          const float* __restrict__ Wo)
{
    size_t i = ((size_t)blockIdx.x * blockDim.x + threadIdx.x) * 4;
    if (i >= SPLIT_TOTAL) return;
    const float* src; __nv_bfloat16 *hi, *lo; size_t off;
    if (i < 8388608)       { src = hs; hi = g_ah;  lo = g_al;  off = i; }
    else if (i < 12582912) { src = Wq; hi = g_wqh; lo = g_wql; off = i - 8388608; }
    else if (i < 13631488) { src = Wk; hi = g_wkh; lo = g_wkl; off = i - 12582912; }
    else if (i < 14680064) { src = Wv; hi = g_wvh; lo = g_wvl; off = i - 13631488; }
    else                   { src = Wo; hi = g_woh; lo = g_wol; off = i - 14680064; }
    float4 v = *(const float4*)(src + off);
    store_split2(hi + off,     lo + off,     v.x, v.y);
    store_split2(hi + off + 2, lo + off + 2, v.z, v.w);
}

// ---------------- RoPE table (double precision trig) ------------------------
__global__ void rope_table_kernel()
{
    int idx = blockIdx.x * blockDim.x + threadIdx.x;
    if (idx >= S_ * 64) return;
    int s = idx >> 6, i = idx & 63;
    double inv = pow(10000.0, -(double)(2 * i) / 128.0);
    double f = (double)s * inv;
    g_cos[idx] = (float)cos(f);
    g_sin[idx] = (float)sin(f);
}

// ---------------- mma.sync bf16x3 GEMM: 256x128 tile, 512 thr, 4-stage -------
#define BKK       32
#define NKI       (H_/BKK)
#define A_SPLIT_B 16384
#define B_SPLIT_B 8192
#define STAGE_B   49152
#define GEMM_SMEM 196608
#define EPI_STR   129

__global__ __launch_bounds__(512) void tc_gemm(int which, float* Cout)
{
    extern __shared__ char smem[];
    const uint32_t sb0 = smem_u32(smem);
    const int tid = threadIdx.x;
    const int wid = tid >> 5, lane = tid & 31;
    const int wm = wid & 3, wn = wid >> 2;       // 4(m) x 4(n) warp grid, 64x32 tiles

    const int m0 = blockIdx.y * 256, n0 = blockIdx.x * 128;

    const __nv_bfloat16 *Ahp, *Alp, *Bhp, *Blp;
    if (which == 0) {
        Ahp = g_ah; Alp = g_al;
        if (n0 < 2048)      { Bhp = g_wqh + (size_t)n0 * H_;        Blp = g_wql + (size_t)n0 * H_; }
        else if (n0 < 2560) { Bhp = g_wkh + (size_t)(n0-2048) * H_; Blp = g_wkl + (size_t)(n0-2048) * H_; }
        else                { Bhp = g_wvh + (size_t)(n0-2560) * H_; Blp = g_wvl + (size_t)(n0-2560) * H_; }
    } else {
        Ahp = g_aoh; Alp = g_aol;
        Bhp = g_woh + (size_t)n0 * H_; Blp = g_wol + (size_t)n0 * H_;
    }

    auto load_stage = [&](int kt, int s) {
        const int k0 = kt * BKK;
        const uint32_t stage = sb0 + s * STAGE_B;
#pragma unroll
        for (int i = 0; i < 6; ++i) {
            int ch = tid + (i << 9);
            if (ch < 2048) {
                int sp = ch >> 10, w = ch & 1023;
                int r = w >> 2, c = w & 3;
                const __nv_bfloat16* src = (sp ? Alp : Ahp) + (size_t)(m0 + r) * H_ + k0 + c * 8;
                CP_ASYNC16(stage + sp * A_SPLIT_B + sw_off(r, c), src);
            } else {
                int ch2 = ch - 2048;
                int sp = ch2 >> 9, w = ch2 & 511;
                int r = w >> 2, c = w & 3;
                const __nv_bfloat16* src = (sp ? Blp : Bhp) + (size_t)r * H_ + k0 + c * 8;
                CP_ASYNC16(stage + 2 * A_SPLIT_B + sp * B_SPLIT_B + sw_off(r, c), src);
            }
        }
        CP_COMMIT();
    };

    float acc[4][4][4];
#pragma unroll
    for (int mi = 0; mi < 4; mi++)
#pragma unroll
        for (int ni = 0; ni < 4; ni++)
#pragma unroll
            for (int e = 0; e < 4; e++) acc[mi][ni][e] = 0.f;

    load_stage(0, 0);
    load_stage(1, 1);
    load_stage(2, 2);

    const int lrow = lane & 15;
    const int lchunk = lane >> 4;

    for (int kt = 0; kt < NKI; ++kt) {
        CP_WAIT2();
        __syncthreads();
        if (kt + 3 < NKI) load_stage(kt + 3, (kt + 3) & 3);
        else              CP_COMMIT();

        const uint32_t stage = sb0 + (kt & 3) * STAGE_B;

#pragma unroll
        for (int kk = 0; kk < 2; ++kk) {
            const int cc = kk * 2 + lchunk;
            uint32_t AHf[4][4], ALf[4][4];
#pragma unroll
            for (int mi = 0; mi < 4; ++mi) {
                int row = wm * 64 + mi * 16 + lrow;
                uint32_t a = stage + sw_off(row, cc);
                LDSM_X4(AHf[mi][0], AHf[mi][1], AHf[mi][2], AHf[mi][3], a);
                LDSM_X4(ALf[mi][0], ALf[mi][1], ALf[mi][2], ALf[mi][3], a + A_SPLIT_B);
            }
            uint32_t BHf[2][4], BLf[2][4];
#pragma unroll
            for (int g = 0; g < 2; ++g) {
                int row = wn * 32 + g * 16 + lrow;
                uint32_t a = stage + 2 * A_SPLIT_B + sw_off(row, cc);
                LDSM_X4(BHf[g][0], BHf[g][1], BHf[g][2], BHf[g][3], a);
                LDSM_X4(BLf[g][0], BLf[g][1], BLf[g][2], BLf[g][3], a + B_SPLIT_B);
            }
#pragma unroll
            for (int mi = 0; mi < 4; ++mi)
#pragma unroll
                for (int ni = 0; ni < 4; ++ni)
                    MMA_BF16(acc[mi][ni], AHf[mi], BHf[ni>>1][ni&1], BHf[ni>>1][(ni&1)+2]);
#pragma unroll
            for (int mi = 0; mi < 4; ++mi)
#pragma unroll
                for (int ni = 0; ni < 4; ++ni)
                    MMA_BF16(acc[mi][ni], AHf[mi], BLf[ni>>1][ni&1], BLf[ni>>1][(ni&1)+2]);
#pragma unroll
            for (int mi = 0; mi < 4; ++mi)
#pragma unroll
                for (int ni = 0; ni < 4; ++ni)
                    MMA_BF16(acc[mi][ni], ALf[mi], BHf[ni>>1][ni&1], BHf[ni>>1][(ni&1)+2]);
        }
    }

    if (which == 1) {
#pragma unroll
        for (int mi = 0; mi < 4; ++mi) {
            const int row = m0 + wm * 64 + mi * 16 + (lane >> 2);
#pragma unroll
            for (int ni = 0; ni < 4; ++ni) {
                const int col = n0 + wn * 32 + ni * 8 + (lane & 3) * 2;
                float* cp = Cout + (size_t)row * 2048 + col;
                *(float2*)cp = make_float2(acc[mi][ni][0], acc[mi][ni][1]);
                *(float2*)(cp + (size_t)8 * 2048) = make_float2(acc[mi][ni][2], acc[mi][ni][3]);
            }
        }
        return;
    }

    // ---- fused QKV epilogue: stage fp32 tile in smem, then RoPE/split/transpose
    CP_WAIT0();
    __syncthreads();
    float* sf = (float*)smem;        // [256][EPI_STR]
#pragma unroll
    for (int mi = 0; mi < 4; ++mi) {
        const int row = wm * 64 + mi * 16 + (lane >> 2);
#pragma unroll
        for (int ni = 0; ni < 4; ++ni) {
            const int col = wn * 32 + ni * 8 + (lane & 3) * 2;
            sf[row * EPI_STR + col]           = acc[mi][ni][0];
            sf[row * EPI_STR + col + 1]       = acc[mi][ni][1];
            sf[(row + 8) * EPI_STR + col]     = acc[mi][ni][2];
            sf[(row + 8) * EPI_STR + col + 1] = acc[mi][ni][3];
        }
    }
    __syncthreads();

    if (n0 >= 2560) {
        const int b = m0 >> 11, s0l = m0 & 2047, hk = (n0 - 2560) >> 7;
#pragma unroll
        for (int it = 0; it < 8; ++it) {
            const int d = it * 16 + wid;
            const size_t ob = ((size_t)(b * NKV_ + hk) * HD_ + d) * S_ + s0l;
#pragma unroll
            for (int k = 0; k < 8; ++k) {
                const int s = lane + 32 * k;
                float x = sf[s * EPI_STR + d];
                __nv_bfloat16 hv = __float2bfloat16(x);
                g_vth[ob + s] = hv;
                g_vtl[ob + s] = __float2bfloat16(x - __bfloat162float(hv));
            }
        }
    } else {
        const bool isq = (n0 < 2048);
        __nv_bfloat16* dh = isq ? g_qh : g_kh;
        __nv_bfloat16* dl = isq ? g_ql : g_kl;
        const int rowstr = isq ? 2048 : 512;
        const int coloff = isq ? n0 : (n0 - 2048);
        const int c = 2 * lane;
        for (int r = wid; r < 256; r += 16) {
            const int m = m0 + r, s = m & (S_ - 1);
            float x1a = sf[r * EPI_STR + c],      x1b = sf[r * EPI_STR + c + 1];
            float x2a = sf[r * EPI_STR + c + 64], x2b = sf[r * EPI_STR + c + 65];
            float2 cs = *(const float2*)(g_cos + s * 64 + c);
            float2 sn = *(const float2*)(g_sin + s * 64 + c);
            float y1a = x1a * cs.x - x2a * sn.x;
            float y1b = x1b * cs.y - x2b * sn.y;
            float y2a = x2a * cs.x + x1a * sn.x;
            float y2b = x2b * cs.y + x1b * sn.y;
            size_t base = (size_t)m * rowstr + coloff;
            store_split2(dh + base + c,      dl + base + c,      y1a, y1b);
            store_split2(dh + base + c + 64, dl + base + c + 64, y2a, y2b);
        }
    }
}

// ---------------- tensor-core causal flash attention (bf16x3, Q in regs) -----
// smem: K bufs 2x32K | Vt bufs 2x32K = 128K. Q staged through [0,64K) pre-loop.
#define FLASH_SMEM 131072

__global__ __launch_bounds__(256) void flash_tc()
{
    extern __shared__ char smem[];
    const uint32_t sb = smem_u32(smem);
    const int tid = threadIdx.x;
    const int wid = tid >> 5, lane = tid & 31;
    const int lrow = lane & 15, lchunk = lane >> 4;
    const int qb = (int)gridDim.x - 1 - (int)blockIdx.x;
    const int h = blockIdx.y, b = blockIdx.z;
    const int hk = h >> 2;
    const int q0 = qb * 128;
    const int wq0 = wid * 16;

    // ---- stage Q in smem [0,64K), then hoist fragments to registers
#pragma unroll
    for (int i = 0; i < 16; ++i) {
        int ch = tid + (i << 8);
        int sp = ch >> 11, w = ch & 2047;
        int r = w >> 4, c16 = w & 15;
        const __nv_bfloat16* src = (sp ? g_ql : g_qh)
            + ((size_t)((b * S_ + q0 + r) * NH_ + h)) * HD_ + c16 * 8;
        CP_ASYNC16(sb + sp * 32768 + (c16 >> 2) * 8192 + sw_off(r, c16 & 3), src);
    }
    CP_COMMIT();
    CP_WAIT0();
    __syncthreads();

    uint32_t QH[8][4], QL[8][4];
#pragma unroll
    for (int kk = 0; kk < 8; ++kk) {
        const int p = kk >> 1, cc = ((kk & 1) << 1) + lchunk;
        uint32_t qa = sb + p * 8192 + sw_off(wq0 + lrow, cc);
        LDSM_X4(QH[kk][0], QH[kk][1], QH[kk][2], QH[kk][3], qa);
        LDSM_X4(QL[kk][0], QL[kk][1], QL[kk][2], QL[kk][3], qa + 32768);
    }
    __syncthreads();     // Q consumed; KV ring may overwrite staging area

    auto load_kv = [&](int jb, int s) {
        const int j0 = jb * 64;
        const uint32_t kb = sb + s * 32768;
        const uint32_t vb = sb + 65536 + s * 32768;
#pragma unroll
        for (int i = 0; i < 16; ++i) {
            int ch = tid + (i << 8);
            if (ch < 2048) {
                int sp = ch >> 10, w = ch & 1023;
                int r = w >> 4, c16 = w & 15;
                const __nv_bfloat16* src = (sp ? g_kl : g_kh)
                    + ((size_t)((b * S_ + j0 + r) * NKV_ + hk)) * HD_ + c16 * 8;
                CP_ASYNC16(kb + sp * 16384 + (c16 >> 2) * 4096 + sw_off(r, c16 & 3), src);
            } else {
                int ch2 = ch - 2048;
                int sp = ch2 >> 10, w = ch2 & 1023;
                int d = w >> 3, c8 = w & 7;
                const __nv_bfloat16* src = (sp ? g_vtl : g_vth)
                    + ((size_t)(b * NKV_ + hk) * HD_ + d) * S_ + j0 + c8 * 8;
                CP_ASYNC16(vb + sp * 16384 + (c8 >> 2) * 8192 + sw_off(d, c8 & 3), src);
            }
        }
        CP_COMMIT();
    };

    load_kv(0, 0);

    float oacc[16][4];
#pragma unroll
    for (int ob = 0; ob < 16; ++ob)
#pragma unroll
        for (int e = 0; e < 4; ++e) oacc[ob][e] = 0.f;
    float m1 = -INFINITY, m2 = -INFINITY, l1 = 0.f, l2 = 0.f;
    const float scale2 = 0.12751726f;              // log2(e)/sqrt(128)
    const int r1g = q0 + wq0 + (lane >> 2);
    const int njb = 2 * qb + 2;

    for (int jb = 0; jb < njb; ++jb) {
        if (jb + 1 < njb) { load_kv(jb + 1, (jb + 1) & 1); CP_WAIT1(); }
        else              { CP_WAIT0(); }
        __syncthreads();
        const uint32_t kb = sb + (jb & 1) * 32768;
        const uint32_t vb = sb + 65536 + (jb & 1) * 32768;
        const int j0 = jb * 64;

        if (j0 <= q0 + wq0 + 15) {
            float sacc[8][4];
#pragma unroll
            for (int nb = 0; nb < 8; ++nb)
#pragma unroll
                for (int e = 0; e < 4; ++e) sacc[nb][e] = 0.f;

#pragma unroll
            for (int kk = 0; kk < 8; ++kk) {
                const int p = kk >> 1, cc = ((kk & 1) << 1) + lchunk;
                uint32_t KH[4][4], KL[4][4];
#pragma unroll
                for (int g = 0; g < 4; ++g) {
                    uint32_t ka = kb + p * 4096 + sw_off(g * 16 + lrow, cc);
                    LDSM_X4(KH[g][0], KH[g][1], KH[g][2], KH[g][3], ka);
                    LDSM_X4(KL[g][0], KL[g][1], KL[g][2], KL[g][3], ka + 16384);
                }
#pragma unroll
                for (int nb = 0; nb < 8; ++nb)
                    MMA_BF16(sacc[nb], QH[kk], KH[nb>>1][nb&1], KH[nb>>1][(nb&1)+2]);
#pragma unroll
                for (int nb = 0; nb < 8; ++nb)
                    MMA_BF16(sacc[nb], QH[kk], KL[nb>>1][nb&1], KL[nb>>1][(nb&1)+2]);
#pragma unroll
                for (int nb = 0; nb < 8; ++nb)
                    MMA_BF16(sacc[nb], QL[kk], KH[nb>>1][nb&1], KH[nb>>1][(nb&1)+2]);
            }

            const bool msk = (j0 + 63 > q0 + wq0);
            float mx1 = -INFINITY, mx2 = -INFINITY;
#pragma unroll
            for (int nb = 0; nb < 8; ++nb) {
                int c0 = j0 + nb * 8 + ((lane & 3) << 1);
                float x0 = sacc[nb][0] * scale2, x1 = sacc[nb][1] * scale2;
                float x2 = sacc[nb][2] * scale2, x3 = sacc[nb][3] * scale2;
                if (msk) {
                    if (c0     > r1g)     x0 = -INFINITY;
                    if (c0 + 1 > r1g)     x1 = -INFINITY;
                    if (c0     > r1g + 8) x2 = -INFINITY;
                    if (c0 + 1 > r1g + 8) x3 = -INFINITY;
                }
                sacc[nb][0] = x0; sacc[nb][1] = x1; sacc[nb][2] = x2; sacc[nb][3] = x3;
                mx1 = fmaxf(mx1, fmaxf(x0, x1));
                mx2 = fmaxf(mx2, fmaxf(x2, x3));
            }
            mx1 = fmaxf(mx1, __shfl_xor_sync(0xffffffffu, mx1, 1));
            mx1 = fmaxf(mx1, __shfl_xor_sync(0xffffffffu, mx1, 2));
            mx2 = fmaxf(mx2, __shfl_xor_sync(0xffffffffu, mx2, 1));
            mx2 = fmaxf(mx2, __shfl_xor_sync(0xffffffffu, mx2, 2));
            float mn1 = fmaxf(m1, mx1), mn2 = fmaxf(m2, mx2);
            float rs1 = 0.f, rs2 = 0.f;
#pragma unroll
            for (int nb = 0; nb < 8; ++nb) {
                float p0 = exp2f(sacc[nb][0] - mn1), p1 = exp2f(sacc[nb][1] - mn1);
                float p2 = exp2f(sacc[nb][2] - mn2), p3 = exp2f(sacc[nb][3] - mn2);
                sacc[nb][0] = p0; sacc[nb][1] = p1; sacc[nb][2] = p2; sacc[nb][3] = p3;
                rs1 += p0 + p1; rs2 += p2 + p3;
            }
            rs1 += __shfl_xor_sync(0xffffffffu, rs1, 1);
            rs1 += __shfl_xor_sync(0xffffffffu, rs1, 2);
            rs2 += __shfl_xor_sync(0xffffffffu, rs2, 1);
            rs2 += __shfl_xor_sync(0xffffffffu, rs2, 2);
            // skip rescale when running max unchanged for the whole warp (cr==1)
            bool nochange = (mn1 == m1) && (mn2 == m2);
            if (!__all_sync(0xffffffffu, nochange)) {
                float cr1 = exp2f(m1 - mn1), cr2 = exp2f(m2 - mn2);
                l1 *= cr1; l2 *= cr2;
#pragma unroll
                for (int ob = 0; ob < 16; ++ob) {
                    oacc[ob][0] *= cr1; oacc[ob][1] *= cr1;
                    oacc[ob][2] *= cr2; oacc[ob][3] *= cr2;
                }
            }
            l1 += rs1; l2 += rs2;
            m1 = mn1; m2 = mn2;

#pragma unroll
            for (int kc = 0; kc < 4; ++kc) {
                uint32_t PH[4], PL[4];
                split_pack(sacc[2*kc][0],   sacc[2*kc][1],   PH[0], PL[0]);
                split_pack(sacc[2*kc][2],   sacc[2*kc][3],   PH[1], PL[1]);
                split_pack(sacc[2*kc+1][0], sacc[2*kc+1][1], PH[2], PL[2]);
                split_pack(sacc[2*kc+1][2], sacc[2*kc+1][3], PH[3], PL[3]);
                const int p = kc >> 1, cc = ((kc & 1) << 1) + lchunk;
#pragma unroll
                for (int g = 0; g < 8; ++g) {
                    uint32_t VH[4], VL[4];
                    uint32_t va = vb + p * 8192 + sw_off(g * 16 + lrow, cc);
                    LDSM_X4(VH[0], VH[1], VH[2], VH[3], va);
                    LDSM_X4(VL[0], VL[1], VL[2], VL[3], va + 16384);
                    MMA_BF16(oacc[2*g],   PH, VH[0], VH[2]);
                    MMA_BF16(oacc[2*g+1], PH, VH[1], VH[3]);
                    MMA_BF16(oacc[2*g],   PH, VL[0], VL[2]);
                    MMA_BF16(oacc[2*g+1], PH, VL[1], VL[3]);
                    MMA_BF16(oacc[2*g],   PL, VH[0], VH[2]);
                    MMA_BF16(oacc[2*g+1], PL, VH[1], VH[3]);
                }
            }
        }
        __syncthreads();
    }

    float i1 = 1.f / l1, i2 = 1.f / l2;
    size_t base1 = (size_t)(b * S_ + r1g) * 2048 + h * 128;
    size_t base2 = base1 + (size_t)8 * 2048;
#pragma unroll
    for (int ob = 0; ob < 16; ++ob) {
        int col = ob * 8 + ((lane & 3) << 1);
        store_split2(g_aoh + base1 + col, g_aol + base1 + col,
                     oacc[ob][0] * i1, oacc[ob][1] * i1);
        store_split2(g_aoh + base2 + col, g_aol + base2 + col,
                     oacc[ob][2] * i2, oacc[ob][3] * i2);
    }
}

// ---------------- launch ----------------------------------------------------
extern "C" void kernel_launch(void* const* d_in, const int* in_sizes, int n_in,
                              void* d_out, int out_size)
{
    (void)in_sizes; (void)n_in; (void)out_size;
    const float* hs = (const float*)d_in[0];
    const float* Wq = (const float*)d_in[1];
    const float* Wk = (const float*)d_in[2];
    const float* Wv = (const float*)d_in[3];
    const float* Wo = (const float*)d_in[4];
    float* out = (float*)d_out;

    cudaFuncSetAttribute(tc_gemm, cudaFuncAttributeMaxDynamicSharedMemorySize, GEMM_SMEM);
    cudaFuncSetAttribute(flash_tc, cudaFuncAttributeMaxDynamicSharedMemorySize, FLASH_SMEM);

    split_all<<<SPLIT_TOTAL / 4 / 256, 256>>>(hs, Wq, Wk, Wv, Wo);
    rope_table_kernel<<<(S_ * 64 + 255) / 256, 256>>>();
    tc_gemm<<<dim3(24, 16), 512, GEMM_SMEM>>>(0, nullptr);
    flash_tc<<<dim3(S_ / 128, NH_, B_), 256, FLASH_SMEM>>>();
    tc_gemm<<<dim3(16, 16), 512, GEMM_SMEM>>>(1, out);
}

// round 11
// speedup vs baseline: 1.2438x; 1.2438x over previous
// FlashSparseAttention — round 10: fp16-single tensor-core flash attention
// (3x fewer attention MMAs) + bf16x3 GEMMs (256-thr, R8 config).
// B=2, S=2048, H=2048, NH=16, NKV=4, HD=128, GQA groups=4, RoPE theta=1e4.
#include <cuda_runtime.h>
#include <cuda_bf16.h>
#include <cuda_fp16.h>
#include <math.h>
#include <stdint.h>

#define B_    2
#define S_    2048
#define H_    2048
#define NH_   16
#define NKV_  4
#define HD_   128
#define M_    (B_*S_)      // 4096 rows

// ---------------- scratch (device globals: allocation-free) ----------------
__device__ float g_cos[S_*64];
__device__ float g_sin[S_*64];

// bf16 hi/lo splits (GEMM operands)
__device__ __align__(16) __nv_bfloat16 g_ah [(size_t)M_*H_],   g_al [(size_t)M_*H_];
__device__ __align__(16) __nv_bfloat16 g_wqh[(size_t)2048*H_], g_wql[(size_t)2048*H_];
__device__ __align__(16) __nv_bfloat16 g_wkh[(size_t)512*H_],  g_wkl[(size_t)512*H_];
__device__ __align__(16) __nv_bfloat16 g_wvh[(size_t)512*H_],  g_wvl[(size_t)512*H_];
__device__ __align__(16) __nv_bfloat16 g_woh[(size_t)2048*H_], g_wol[(size_t)2048*H_];
__device__ __align__(16) __nv_bfloat16 g_aoh[(size_t)M_*2048], g_aol[(size_t)M_*2048];
// attention operands: fp16 single precision
__device__ __align__(16) __half g_qh [(size_t)M_*NH_*HD_];
__device__ __align__(16) __half g_kh [(size_t)M_*NKV_*HD_];
__device__ __align__(16) __half g_vth[(size_t)M_*NKV_*HD_];   // [b][hk][hd][s]

// ---------------- PTX helpers ------------------------------------------------
__device__ __forceinline__ uint32_t smem_u32(const void* p) {
    uint32_t a;
    asm("{ .reg .u64 t; cvta.to.shared.u64 t, %1; cvt.u32.u64 %0, t; }" : "=r"(a) : "l"(p));
    return a;
}
#define CP_ASYNC16(dst, src) \
    asm volatile("cp.async.cg.shared.global [%0], [%1], 16;" :: "r"(dst), "l"(src) : "memory")
#define CP_COMMIT()  asm volatile("cp.async.commit_group;" ::: "memory")
#define CP_WAIT0()   asm volatile("cp.async.wait_group 0;" ::: "memory")
#define CP_WAIT1()   asm volatile("cp.async.wait_group 1;" ::: "memory")
#define CP_WAIT2()   asm volatile("cp.async.wait_group 2;" ::: "memory")

#define LDSM_X4(r0, r1, r2, r3, addr) \
    asm volatile("ldmatrix.sync.aligned.m8n8.x4.shared.b16 {%0,%1,%2,%3}, [%4];" \
        : "=r"(r0), "=r"(r1), "=r"(r2), "=r"(r3) : "r"(addr))

#define MMA_BF16(d, a, b0, b1) \
    asm volatile("mma.sync.aligned.m16n8k16.row.col.f32.bf16.bf16.f32 " \
        "{%0,%1,%2,%3}, {%4,%5,%6,%7}, {%8,%9}, {%0,%1,%2,%3};" \
        : "+f"((d)[0]), "+f"((d)[1]), "+f"((d)[2]), "+f"((d)[3]) \
        : "r"((a)[0]), "r"((a)[1]), "r"((a)[2]), "r"((a)[3]), "r"(b0), "r"(b1))

#define MMA_F16(d, a, b0, b1) \
    asm volatile("mma.sync.aligned.m16n8k16.row.col.f32.f16.f16.f32 " \
        "{%0,%1,%2,%3}, {%4,%5,%6,%7}, {%8,%9}, {%0,%1,%2,%3};" \
        : "+f"((d)[0]), "+f"((d)[1]), "+f"((d)[2]), "+f"((d)[3]) \
        : "r"((a)[0]), "r"((a)[1]), "r"((a)[2]), "r"((a)[3]), "r"(b0), "r"(b1))

__device__ __forceinline__ uint32_t sw_off(int row, int chunk) {
    return (uint32_t)(row * 64 + ((chunk ^ ((row >> 1) & 3)) << 4));
}
__device__ __forceinline__ void store_split2(__nv_bfloat16* hp, __nv_bfloat16* lp,
                                             float a, float b) {
    __nv_bfloat16 ha = __float2bfloat16(a), hb = __float2bfloat16(b);
    __nv_bfloat162 hh; hh.x = ha; hh.y = hb; *(__nv_bfloat162*)hp = hh;
    __nv_bfloat162 ll;
    ll.x = __float2bfloat16(a - __bfloat162float(ha));
    ll.y = __float2bfloat16(b - __bfloat162float(hb));
    *(__nv_bfloat162*)lp = ll;
}
__device__ __forceinline__ uint32_t pack_h2(float a, float b) {
    __half2 h = __floats2half2_rn(a, b);
    return *(uint32_t*)&h;
}

// ---------------- merged bf16 split for all 5 inputs --------------------------
#define SPLIT_TOTAL 18874368
__global__ void split_all(const float* __restrict__ hs, const float* __restrict__ Wq,
                          const float* __restrict__ Wk, const float* __restrict__ Wv,
                          const float* __restrict__ Wo)
{
    size_t i = ((size_t)blockIdx.x * blockDim.x + threadIdx.x) * 4;
    if (i >= SPLIT_TOTAL) return;
    const float* src; __nv_bfloat16 *hi, *lo; size_t off;
    if (i < 8388608)       { src = hs; hi = g_ah;  lo = g_al;  off = i; }
    else if (i < 12582912) { src = Wq; hi = g_wqh; lo = g_wql; off = i - 8388608; }
    else if (i < 13631488) { src = Wk; hi = g_wkh; lo = g_wkl; off = i - 12582912; }
    else if (i < 14680064) { src = Wv; hi = g_wvh; lo = g_wvl; off = i - 13631488; }
    else                   { src = Wo; hi = g_woh; lo = g_wol; off = i - 14680064; }
    float4 v = *(const float4*)(src + off);
    store_split2(hi + off,     lo + off,     v.x, v.y);
    store_split2(hi + off + 2, lo + off + 2, v.z, v.w);
}

// ---------------- RoPE table (double precision trig) ------------------------
__global__ void rope_table_kernel()
{
    int idx = blockIdx.x * blockDim.x + threadIdx.x;
    if (idx >= S_ * 64) return;
    int s = idx >> 6, i = idx & 63;
    double inv = pow(10000.0, -(double)(2 * i) / 128.0);
    double f = (double)s * inv;
    g_cos[idx] = (float)cos(f);
    g_sin[idx] = (float)sin(f);
}

// ---------------- mma.sync bf16x3 GEMM, 256x128 tile, 256 thr, 4-stage -------
// which==0: fused QKV; epilogue applies RoPE + fp16 store (q,k) / fp16 transpose (v)
// which==1: O projection -> fp32 Cout.
#define BKK       32
#define NKI       (H_/BKK)
#define A_SPLIT_B 16384
#define B_SPLIT_B 8192
#define STAGE_B   49152
#define GEMM_SMEM 196608
#define EPI_STR   129

__global__ __launch_bounds__(256) void tc_gemm(int which, float* Cout)
{
    extern __shared__ char smem[];
    const uint32_t sb0 = smem_u32(smem);
    const int tid = threadIdx.x;
    const int wid = tid >> 5, lane = tid & 31;
    const int wm = wid & 3, wn = wid >> 2;        // 4(m) x 2(n), warp tile 64x64

    const int m0 = blockIdx.y * 256, n0 = blockIdx.x * 128;

    const __nv_bfloat16 *Ahp, *Alp, *Bhp, *Blp;
    if (which == 0) {
        Ahp = g_ah; Alp = g_al;
        if (n0 < 2048)      { Bhp = g_wqh + (size_t)n0 * H_;        Blp = g_wql + (size_t)n0 * H_; }
        else if (n0 < 2560) { Bhp = g_wkh + (size_t)(n0-2048) * H_; Blp = g_wkl + (size_t)(n0-2048) * H_; }
        else                { Bhp = g_wvh + (size_t)(n0-2560) * H_; Blp = g_wvl + (size_t)(n0-2560) * H_; }
    } else {
        Ahp = g_aoh; Alp = g_aol;
        Bhp = g_woh + (size_t)n0 * H_; Blp = g_wol + (size_t)n0 * H_;
    }

    auto load_stage = [&](int kt, int s) {
        const int k0 = kt * BKK;
        const uint32_t stage = sb0 + s * STAGE_B;
#pragma unroll
        for (int i = 0; i < 12; ++i) {
            int ch = tid + (i << 8);
            if (ch < 2048) {
                int sp = ch >> 10, w = ch & 1023;
                int r = w >> 2, c = w & 3;
                const __nv_bfloat16* src = (sp ? Alp : Ahp) + (size_t)(m0 + r) * H_ + k0 + c * 8;
                CP_ASYNC16(stage + sp * A_SPLIT_B + sw_off(r, c), src);
            } else {
                int ch2 = ch - 2048;
                int sp = ch2 >> 9, w = ch2 & 511;
                int r = w >> 2, c = w & 3;
                const __nv_bfloat16* src = (sp ? Blp : Bhp) + (size_t)r * H_ + k0 + c * 8;
                CP_ASYNC16(stage + 2 * A_SPLIT_B + sp * B_SPLIT_B + sw_off(r, c), src);
            }
        }
        CP_COMMIT();
    };

    float acc[4][8][4];
#pragma unroll
    for (int mi = 0; mi < 4; mi++)
#pragma unroll
        for (int ni = 0; ni < 8; ni++)
#pragma unroll
            for (int e = 0; e < 4; e++) acc[mi][ni][e] = 0.f;

    load_stage(0, 0);
    load_stage(1, 1);
    load_stage(2, 2);

    const int lrow = lane & 15;
    const int lchunk = lane >> 4;

    for (int kt = 0; kt < NKI; ++kt) {
        CP_WAIT2();
        __syncthreads();
        if (kt + 3 < NKI) load_stage(kt + 3, (kt + 3) & 3);
        else              CP_COMMIT();

        const uint32_t stage = sb0 + (kt & 3) * STAGE_B;

#pragma unroll
        for (int kk = 0; kk < 2; ++kk) {
            const int cc = kk * 2 + lchunk;
            uint32_t AHf[4][4], ALf[4][4];
#pragma unroll
            for (int mi = 0; mi < 4; ++mi) {
                int row = wm * 64 + mi * 16 + lrow;
                uint32_t a = stage + sw_off(row, cc);
                LDSM_X4(AHf[mi][0], AHf[mi][1], AHf[mi][2], AHf[mi][3], a);
                LDSM_X4(ALf[mi][0], ALf[mi][1], ALf[mi][2], ALf[mi][3], a + A_SPLIT_B);
            }
            uint32_t BHf[4][4], BLf[4][4];
#pragma unroll
            for (int g = 0; g < 4; ++g) {
                int row = wn * 64 + g * 16 + lrow;
                uint32_t a = stage + 2 * A_SPLIT_B + sw_off(row, cc);
                LDSM_X4(BHf[g][0], BHf[g][1], BHf[g][2], BHf[g][3], a);
                LDSM_X4(BLf[g][0], BLf[g][1], BLf[g][2], BLf[g][3], a + B_SPLIT_B);
            }
#pragma unroll
            for (int mi = 0; mi < 4; ++mi)
#pragma unroll
                for (int ni = 0; ni < 8; ++ni)
                    MMA_BF16(acc[mi][ni], AHf[mi], BHf[ni>>1][ni&1], BHf[ni>>1][(ni&1)+2]);
#pragma unroll
            for (int mi = 0; mi < 4; ++mi)
#pragma unroll
                for (int ni = 0; ni < 8; ++ni)
                    MMA_BF16(acc[mi][ni], AHf[mi], BLf[ni>>1][ni&1], BLf[ni>>1][(ni&1)+2]);
#pragma unroll
            for (int mi = 0; mi < 4; ++mi)
#pragma unroll
                for (int ni = 0; ni < 8; ++ni)
                    MMA_BF16(acc[mi][ni], ALf[mi], BHf[ni>>1][ni&1], BHf[ni>>1][(ni&1)+2]);
        }
    }

    if (which == 1) {
#pragma unroll
        for (int mi = 0; mi < 4; ++mi) {
            const int row = m0 + wm * 64 + mi * 16 + (lane >> 2);
#pragma unroll
            for (int ni = 0; ni < 8; ++ni) {
                const int col = n0 + wn * 64 + ni * 8 + (lane & 3) * 2;
                float* cp = Cout + (size_t)row * 2048 + col;
                *(float2*)cp = make_float2(acc[mi][ni][0], acc[mi][ni][1]);
                *(float2*)(cp + (size_t)8 * 2048) = make_float2(acc[mi][ni][2], acc[mi][ni][3]);
            }
        }
        return;
    }

    // ---- fused QKV epilogue: stage fp32 tile in smem, then RoPE/fp16/transpose
    CP_WAIT0();
    __syncthreads();
    float* sf = (float*)smem;        // [256][EPI_STR]
#pragma unroll
    for (int mi = 0; mi < 4; ++mi) {
        const int row = wm * 64 + mi * 16 + (lane >> 2);
#pragma unroll
        for (int ni = 0; ni < 8; ++ni) {
            const int col = wn * 64 + ni * 8 + (lane & 3) * 2;
            sf[row * EPI_STR + col]           = acc[mi][ni][0];
            sf[row * EPI_STR + col + 1]       = acc[mi][ni][1];
            sf[(row + 8) * EPI_STR + col]     = acc[mi][ni][2];
            sf[(row + 8) * EPI_STR + col + 1] = acc[mi][ni][3];
        }
    }
    __syncthreads();

    if (n0 >= 2560) {
        // V region: transpose to fp16 vth [b][hk][d][s]
        const int b = m0 >> 11, s0l = m0 & 2047, hk = (n0 - 2560) >> 7;
#pragma unroll
        for (int it = 0; it < 16; ++it) {
            const int d = it * 8 + wid;
            const size_t ob = ((size_t)(b * NKV_ + hk) * HD_ + d) * S_ + s0l;
#pragma unroll
            for (int k = 0; k < 8; ++k) {
                const int s = lane + 32 * k;
                g_vth[ob + s] = __float2half_rn(sf[s * EPI_STR + d]);
            }
        }
    } else {
        // Q or K region: RoPE + fp16 store
        const bool isq = (n0 < 2048);
        __half* dh = isq ? g_qh : g_kh;
        const int rowstr = isq ? 2048 : 512;
        const int coloff = isq ? n0 : (n0 - 2048);
        const int c = 2 * lane;
        for (int r = wid; r < 256; r += 8) {
            const int m = m0 + r, s = m & (S_ - 1);
            float x1a = sf[r * EPI_STR + c],      x1b = sf[r * EPI_STR + c + 1];
            float x2a = sf[r * EPI_STR + c + 64], x2b = sf[r * EPI_STR + c + 65];
            float2 cs = *(const float2*)(g_cos + s * 64 + c);
            float2 sn = *(const float2*)(g_sin + s * 64 + c);
            float y1a = x1a * cs.x - x2a * sn.x;
            float y1b = x1b * cs.y - x2b * sn.y;
            float y2a = x2a * cs.x + x1a * sn.x;
            float y2b = x2b * cs.y + x1b * sn.y;
            size_t base = (size_t)m * rowstr + coloff;
            *(__half2*)(dh + base + c)      = __floats2half2_rn(y1a, y1b);
            *(__half2*)(dh + base + c + 64) = __floats2half2_rn(y2a, y2b);
        }
    }
}

// ---------------- fp16 tensor-core causal flash attention --------------------
// CTA: 128 q-rows, 8 warps x 16 rows. Q hoisted to regs (fp16, 32 regs).
// smem: K ring 2x16K [0,32K) | V ring 2x16K [32K,64K). Q staged in [0,32K) first.
#define FLASH_SMEM 65536

__global__ __launch_bounds__(256) void flash_tc()
{
    extern __shared__ char smem[];
    const uint32_t sb = smem_u32(smem);
    const int tid = threadIdx.x;
    const int wid = tid >> 5, lane = tid & 31;
    const int lrow = lane & 15, lchunk = lane >> 4;
    const int qb = (int)gridDim.x - 1 - (int)blockIdx.x;   // big blocks first
    const int h = blockIdx.y, b = blockIdx.z;
    const int hk = h >> 2;
    const int q0 = qb * 128;
    const int wq0 = wid * 16;

    // ---- stage Q (fp16, 32KB), hoist fragments, then release staging area
#pragma unroll
    for (int i = 0; i < 8; ++i) {
        int ch = tid + (i << 8);
        int r = ch >> 4, c16 = ch & 15;
        const __half* src = g_qh + ((size_t)((b * S_ + q0 + r) * NH_ + h)) * HD_ + c16 * 8;
        CP_ASYNC16(sb + (c16 >> 2) * 8192 + sw_off(r, c16 & 3), src);
    }
    CP_COMMIT();
    CP_WAIT0();
    __syncthreads();

    uint32_t QH[8][4];
#pragma unroll
    for (int kk = 0; kk < 8; ++kk) {
        const int p = kk >> 1, cc = ((kk & 1) << 1) + lchunk;
        uint32_t qa = sb + p * 8192 + sw_off(wq0 + lrow, cc);
        LDSM_X4(QH[kk][0], QH[kk][1], QH[kk][2], QH[kk][3], qa);
    }
    __syncthreads();     // Q consumed; KV ring may overwrite

    auto load_kv = [&](int jb, int s) {
        const int j0 = jb * 64;
        const uint32_t kb = sb + s * 16384;
        const uint32_t vb = sb + 32768 + s * 16384;
#pragma unroll
        for (int i = 0; i < 8; ++i) {
            int ch = tid + (i << 8);
            if (ch < 1024) {                 // K: 64 rows x 16 chunks
                int r = ch >> 4, c16 = ch & 15;
                const __half* src = g_kh
                    + ((size_t)((b * S_ + j0 + r) * NKV_ + hk)) * HD_ + c16 * 8;
                CP_ASYNC16(kb + (c16 >> 2) * 4096 + sw_off(r, c16 & 3), src);
            } else {                         // Vt: 128 rows(d) x 8 chunks
                int ch2 = ch - 1024;
                int d = ch2 >> 3, c8 = ch2 & 7;
                const __half* src = g_vth
                    + ((size_t)(b * NKV_ + hk) * HD_ + d) * S_ + j0 + c8 * 8;
                CP_ASYNC16(vb + (c8 >> 2) * 8192 + sw_off(d, c8 & 3), src);
            }
        }
        CP_COMMIT();
    };

    load_kv(0, 0);

    float oacc[16][4];
#pragma unroll
    for (int ob = 0; ob < 16; ++ob)
#pragma unroll
        for (int e = 0; e < 4; ++e) oacc[ob][e] = 0.f;
    float m1 = -INFINITY, m2 = -INFINITY, l1 = 0.f, l2 = 0.f;
    const float scale2 = 0.12751726f;              // log2(e)/sqrt(128)
    const int r1g = q0 + wq0 + (lane >> 2);
    const int njb = 2 * qb + 2;

    for (int jb = 0; jb < njb; ++jb) {
        if (jb + 1 < njb) { load_kv(jb + 1, (jb + 1) & 1); CP_WAIT1(); }
        else              { CP_WAIT0(); }
        __syncthreads();
        const uint32_t kb = sb + (jb & 1) * 16384;
        const uint32_t vb = sb + 32768 + (jb & 1) * 16384;
        const int j0 = jb * 64;

        if (j0 <= q0 + wq0 + 15) {
            // ---- S = Q K^T (fp16 single)
            float sacc[8][4];
#pragma unroll
            for (int nb = 0; nb < 8; ++nb)
#pragma unroll
                for (int e = 0; e < 4; ++e) sacc[nb][e] = 0.f;

#pragma unroll
            for (int kk = 0; kk < 8; ++kk) {
                const int p = kk >> 1, cc = ((kk & 1) << 1) + lchunk;
                uint32_t KH[4][4];
#pragma unroll
                for (int g = 0; g < 4; ++g) {
                    uint32_t ka = kb + p * 4096 + sw_off(g * 16 + lrow, cc);
                    LDSM_X4(KH[g][0], KH[g][1], KH[g][2], KH[g][3], ka);
                }
#pragma unroll
                for (int nb = 0; nb < 8; ++nb)
                    MMA_F16(sacc[nb], QH[kk], KH[nb>>1][nb&1], KH[nb>>1][(nb&1)+2]);
            }

            // ---- online softmax (exp2 domain)
            const bool msk = (j0 + 63 > q0 + wq0);
            float mx1 = -INFINITY, mx2 = -INFINITY;
#pragma unroll
            for (int nb = 0; nb < 8; ++nb) {
                int c0 = j0 + nb * 8 + ((lane & 3) << 1);
                float x0 = sacc[nb][0] * scale2, x1 = sacc[nb][1] * scale2;
                float x2 = sacc[nb][2] * scale2, x3 = sacc[nb][3] * scale2;
                if (msk) {
                    if (c0     > r1g)     x0 = -INFINITY;
                    if (c0 + 1 > r1g)     x1 = -INFINITY;
                    if (c0     > r1g + 8) x2 = -INFINITY;
                    if (c0 + 1 > r1g + 8) x3 = -INFINITY;
                }
                sacc[nb][0] = x0; sacc[nb][1] = x1; sacc[nb][2] = x2; sacc[nb][3] = x3;
                mx1 = fmaxf(mx1, fmaxf(x0, x1));
                mx2 = fmaxf(mx2, fmaxf(x2, x3));
            }
            mx1 = fmaxf(mx1, __shfl_xor_sync(0xffffffffu, mx1, 1));
            mx1 = fmaxf(mx1, __shfl_xor_sync(0xffffffffu, mx1, 2));
            mx2 = fmaxf(mx2, __shfl_xor_sync(0xffffffffu, mx2, 1));
            mx2 = fmaxf(mx2, __shfl_xor_sync(0xffffffffu, mx2, 2));
            float mn1 = fmaxf(m1, mx1), mn2 = fmaxf(m2, mx2);
            float rs1 = 0.f, rs2 = 0.f;
#pragma unroll
            for (int nb = 0; nb < 8; ++nb) {
                float p0 = exp2f(sacc[nb][0] - mn1), p1 = exp2f(sacc[nb][1] - mn1);
                float p2 = exp2f(sacc[nb][2] - mn2), p3 = exp2f(sacc[nb][3] - mn2);
                sacc[nb][0] = p0; sacc[nb][1] = p1; sacc[nb][2] = p2; sacc[nb][3] = p3;
                rs1 += p0 + p1; rs2 += p2 + p3;
            }
            rs1 += __shfl_xor_sync(0xffffffffu, rs1, 1);
            rs1 += __shfl_xor_sync(0xffffffffu, rs1, 2);
            rs2 += __shfl_xor_sync(0xffffffffu, rs2, 1);
            rs2 += __shfl_xor_sync(0xffffffffu, rs2, 2);
            bool nochange = (mn1 == m1) && (mn2 == m2);
            if (!__all_sync(0xffffffffu, nochange)) {
                float cr1 = exp2f(m1 - mn1), cr2 = exp2f(m2 - mn2);
                l1 *= cr1; l2 *= cr2;
#pragma unroll
                for (int ob = 0; ob < 16; ++ob) {
                    oacc[ob][0] *= cr1; oacc[ob][1] *= cr1;
                    oacc[ob][2] *= cr2; oacc[ob][3] *= cr2;
                }
            }
            l1 += rs1; l2 += rs2;
            m1 = mn1; m2 = mn2;

            // ---- O += P V (fp16 single, P packed from registers)
#pragma unroll
            for (int kc = 0; kc < 4; ++kc) {
                uint32_t PH[4];
                PH[0] = pack_h2(sacc[2*kc][0],   sacc[2*kc][1]);
                PH[1] = pack_h2(sacc[2*kc][2],   sacc[2*kc][3]);
                PH[2] = pack_h2(sacc[2*kc+1][0], sacc[2*kc+1][1]);
                PH[3] = pack_h2(sacc[2*kc+1][2], sacc[2*kc+1][3]);
                const int p = kc >> 1, cc = ((kc & 1) << 1) + lchunk;
#pragma unroll
                for (int g = 0; g < 8; ++g) {
                    uint32_t VH[4];
                    uint32_t va = vb + p * 8192 + sw_off(g * 16 + lrow, cc);
                    LDSM_X4(VH[0], VH[1], VH[2], VH[3], va);
                    MMA_F16(oacc[2*g],   PH, VH[0], VH[2]);
                    MMA_F16(oacc[2*g+1], PH, VH[1], VH[3]);
                }
            }
        }
        __syncthreads();
    }

    // ---- epilogue: normalize + bf16 split-write to aoh/aol (O-proj stays bf16x3)
    float i1 = 1.f / l1, i2 = 1.f / l2;
    size_t base1 = (size_t)(b * S_ + r1g) * 2048 + h * 128;
    size_t base2 = base1 + (size_t)8 * 2048;
#pragma unroll
    for (int ob = 0; ob < 16; ++ob) {
        int col = ob * 8 + ((lane & 3) << 1);
        store_split2(g_aoh + base1 + col, g_aol + base1 + col,
                     oacc[ob][0] * i1, oacc[ob][1] * i1);
        store_split2(g_aoh + base2 + col, g_aol + base2 + col,
                     oacc[ob][2] * i2, oacc[ob][3] * i2);
    }
}

// ---------------- launch ----------------------------------------------------
extern "C" void kernel_launch(void* const* d_in, const int* in_sizes, int n_in,
                              void* d_out, int out_size)
{
    (void)in_sizes; (void)n_in; (void)out_size;
    const float* hs = (const float*)d_in[0];
    const float* Wq = (const float*)d_in[1];
    const float* Wk = (const float*)d_in[2];
    const float* Wv = (const float*)d_in[3];
    const float* Wo = (const float*)d_in[4];
    float* out = (float*)d_out;

    cudaFuncSetAttribute(tc_gemm, cudaFuncAttributeMaxDynamicSharedMemorySize, GEMM_SMEM);
    cudaFuncSetAttribute(flash_tc, cudaFuncAttributeMaxDynamicSharedMemorySize, FLASH_SMEM);

    split_all<<<SPLIT_TOTAL / 4 / 256, 256>>>(hs, Wq, Wk, Wv, Wo);
    rope_table_kernel<<<(S_ * 64 + 255) / 256, 256>>>();
    tc_gemm<<<dim3(24, 16), 256, GEMM_SMEM>>>(0, nullptr);
    flash_tc<<<dim3(S_ / 128, NH_, B_), 256, FLASH_SMEM>>>();
    tc_gemm<<<dim3(16, 16), 256, GEMM_SMEM>>>(1, out);
}

// round 12
// speedup vs baseline: 1.6090x; 1.2936x over previous
// FlashSparseAttention — round 11: fp16 2-product GEMMs (A hi/lo split x single-fp16 B)
// + fp16 tensor-core flash attention.
// B=2, S=2048, H=2048, NH=16, NKV=4, HD=128, GQA groups=4, RoPE theta=1e4.
#include <cuda_runtime.h>
#include <cuda_bf16.h>
#include <cuda_fp16.h>
#include <math.h>
#include <stdint.h>

#define B_    2
#define S_    2048
#define H_    2048
#define NH_   16
#define NKV_  4
#define HD_   128
#define M_    (B_*S_)      // 4096 rows

// ---------------- scratch (device globals: allocation-free) ----------------
__device__ float g_cos[S_*64];
__device__ float g_sin[S_*64];

// fp16 operands
__device__ __align__(16) __half g_ah [(size_t)M_*H_],   g_al [(size_t)M_*H_];   // hs hi/lo
__device__ __align__(16) __half g_wq [(size_t)2048*H_];
__device__ __align__(16) __half g_wk [(size_t)512*H_];
__device__ __align__(16) __half g_wv [(size_t)512*H_];
__device__ __align__(16) __half g_wo [(size_t)2048*H_];
__device__ __align__(16) __half g_aoh[(size_t)M_*2048], g_aol[(size_t)M_*2048]; // attn out hi/lo
// attention operands (fp16 single)
__device__ __align__(16) __half g_qh [(size_t)M_*NH_*HD_];
__device__ __align__(16) __half g_kh [(size_t)M_*NKV_*HD_];
__device__ __align__(16) __half g_vth[(size_t)M_*NKV_*HD_];   // [b][hk][hd][s]

// ---------------- PTX helpers ------------------------------------------------
__device__ __forceinline__ uint32_t smem_u32(const void* p) {
    uint32_t a;
    asm("{ .reg .u64 t; cvta.to.shared.u64 t, %1; cvt.u32.u64 %0, t; }" : "=r"(a) : "l"(p));
    return a;
}
#define CP_ASYNC16(dst, src) \
    asm volatile("cp.async.cg.shared.global [%0], [%1], 16;" :: "r"(dst), "l"(src) : "memory")
#define CP_COMMIT()  asm volatile("cp.async.commit_group;" ::: "memory")
#define CP_WAIT0()   asm volatile("cp.async.wait_group 0;" ::: "memory")
#define CP_WAIT1()   asm volatile("cp.async.wait_group 1;" ::: "memory")
#define CP_WAIT2()   asm volatile("cp.async.wait_group 2;" ::: "memory")

#define LDSM_X4(r0, r1, r2, r3, addr) \
    asm volatile("ldmatrix.sync.aligned.m8n8.x4.shared.b16 {%0,%1,%2,%3}, [%4];" \
        : "=r"(r0), "=r"(r1), "=r"(r2), "=r"(r3) : "r"(addr))

#define MMA_F16(d, a, b0, b1) \
    asm volatile("mma.sync.aligned.m16n8k16.row.col.f32.f16.f16.f32 " \
        "{%0,%1,%2,%3}, {%4,%5,%6,%7}, {%8,%9}, {%0,%1,%2,%3};" \
        : "+f"((d)[0]), "+f"((d)[1]), "+f"((d)[2]), "+f"((d)[3]) \
        : "r"((a)[0]), "r"((a)[1]), "r"((a)[2]), "r"((a)[3]), "r"(b0), "r"(b1))

__device__ __forceinline__ uint32_t sw_off(int row, int chunk) {
    return (uint32_t)(row * 64 + ((chunk ^ ((row >> 1) & 3)) << 4));
}
__device__ __forceinline__ void store_split2h(__half* hp, __half* lp, float a, float b) {
    __half ha = __float2half_rn(a), hb = __float2half_rn(b);
    *(__half2*)hp = __halves2half2(ha, hb);
    *(__half2*)lp = __halves2half2(__float2half_rn(a - __half2float(ha)),
                                   __float2half_rn(b - __half2float(hb)));
}
__device__ __forceinline__ uint32_t pack_h2(float a, float b) {
    __half2 h = __floats2half2_rn(a, b);
    return *(uint32_t*)&h;
}

// ---------------- merged fp16 split/convert for all 5 inputs ------------------
// hs -> fp16 hi/lo split; weights -> single fp16.
#define SPLIT_TOTAL 18874368
__global__ void split_all(const float* __restrict__ hs, const float* __restrict__ Wq,
                          const float* __restrict__ Wk, const float* __restrict__ Wv,
                          const float* __restrict__ Wo)
{
    size_t i = ((size_t)blockIdx.x * blockDim.x + threadIdx.x) * 4;
    if (i >= SPLIT_TOTAL) return;
    if (i < 8388608) {
        float4 v = *(const float4*)(hs + i);
        store_split2h(g_ah + i,     g_al + i,     v.x, v.y);
        store_split2h(g_ah + i + 2, g_al + i + 2, v.z, v.w);
    } else {
        const float* src; __half* dst; size_t off;
        if (i < 12582912)      { src = Wq; dst = g_wq; off = i - 8388608; }
        else if (i < 13631488) { src = Wk; dst = g_wk; off = i - 12582912; }
        else if (i < 14680064) { src = Wv; dst = g_wv; off = i - 13631488; }
        else                   { src = Wo; dst = g_wo; off = i - 14680064; }
        float4 v = *(const float4*)(src + off);
        *(__half2*)(dst + off)     = __floats2half2_rn(v.x, v.y);
        *(__half2*)(dst + off + 2) = __floats2half2_rn(v.z, v.w);
    }
}

// ---------------- RoPE table (double precision trig) ------------------------
__global__ void rope_table_kernel()
{
    int idx = blockIdx.x * blockDim.x + threadIdx.x;
    if (idx >= S_ * 64) return;
    int s = idx >> 6, i = idx & 63;
    double inv = pow(10000.0, -(double)(2 * i) / 128.0);
    double f = (double)s * inv;
    g_cos[idx] = (float)cos(f);
    g_sin[idx] = (float)sin(f);
}

// ---------------- fp16 2-product GEMM, 256x128 tile, 256 thr, 4-stage --------
// C[M,N] = (Ah+Al)[M,K] * B[N,K]^T, B single fp16 (its rounding is the only drop).
// Smem stage: Ah(16K)|Al(16K)|B(8K) = 40KB, 4 stages = 160KB.
#define BKK       32
#define NKI       (H_/BKK)
#define A_SPLIT_B 16384
#define B_TILE_B  8192
#define STAGE_B   40960
#define GEMM_SMEM 163840
#define EPI_STR   129

__global__ __launch_bounds__(256) void tc_gemm(int which, float* Cout)
{
    extern __shared__ char smem[];
    const uint32_t sb0 = smem_u32(smem);
    const int tid = threadIdx.x;
    const int wid = tid >> 5, lane = tid & 31;
    const int wm = wid & 3, wn = wid >> 2;        // 4(m) x 2(n), warp tile 64x64

    const int m0 = blockIdx.y * 256, n0 = blockIdx.x * 128;

    const __half *Ahp, *Alp, *Bp;
    if (which == 0) {
        Ahp = g_ah; Alp = g_al;
        if (n0 < 2048)      Bp = g_wq + (size_t)n0 * H_;
        else if (n0 < 2560) Bp = g_wk + (size_t)(n0 - 2048) * H_;
        else                Bp = g_wv + (size_t)(n0 - 2560) * H_;
    } else {
        Ahp = g_aoh; Alp = g_aol;
        Bp = g_wo + (size_t)n0 * H_;
    }

    // stage load: A 2048 chunks (2 splits x 256 rows x 4) + B 512 chunks = 2560
    auto load_stage = [&](int kt, int s) {
        const int k0 = kt * BKK;
        const uint32_t stage = sb0 + s * STAGE_B;
#pragma unroll
        for (int i = 0; i < 10; ++i) {
            int ch = tid + (i << 8);
            if (ch < 2048) {
                int sp = ch >> 10, w = ch & 1023;
                int r = w >> 2, c = w & 3;
                const __half* src = (sp ? Alp : Ahp) + (size_t)(m0 + r) * H_ + k0 + c * 8;
                CP_ASYNC16(stage + sp * A_SPLIT_B + sw_off(r, c), src);
            } else {
                int w = ch - 2048;
                int r = w >> 2, c = w & 3;
                const __half* src = Bp + (size_t)r * H_ + k0 + c * 8;
                CP_ASYNC16(stage + 2 * A_SPLIT_B + sw_off(r, c), src);
            }
        }
        CP_COMMIT();
    };

    float acc[4][8][4];
#pragma unroll
    for (int mi = 0; mi < 4; mi++)
#pragma unroll
        for (int ni = 0; ni < 8; ni++)
#pragma unroll
            for (int e = 0; e < 4; e++) acc[mi][ni][e] = 0.f;

    load_stage(0, 0);
    load_stage(1, 1);
    load_stage(2, 2);

    const int lrow = lane & 15;
    const int lchunk = lane >> 4;

    for (int kt = 0; kt < NKI; ++kt) {
        CP_WAIT2();
        __syncthreads();
        if (kt + 3 < NKI) load_stage(kt + 3, (kt + 3) & 3);
        else              CP_COMMIT();

        const uint32_t stage = sb0 + (kt & 3) * STAGE_B;

#pragma unroll
        for (int kk = 0; kk < 2; ++kk) {
            const int cc = kk * 2 + lchunk;
            uint32_t AHf[4][4], ALf[4][4];
#pragma unroll
            for (int mi = 0; mi < 4; ++mi) {
                int row = wm * 64 + mi * 16 + lrow;
                uint32_t a = stage + sw_off(row, cc);
                LDSM_X4(AHf[mi][0], AHf[mi][1], AHf[mi][2], AHf[mi][3], a);
                LDSM_X4(ALf[mi][0], ALf[mi][1], ALf[mi][2], ALf[mi][3], a + A_SPLIT_B);
            }
            uint32_t Bf[4][4];
#pragma unroll
            for (int g = 0; g < 4; ++g) {
                int row = wn * 64 + g * 16 + lrow;
                uint32_t a = stage + 2 * A_SPLIT_B + sw_off(row, cc);
                LDSM_X4(Bf[g][0], Bf[g][1], Bf[g][2], Bf[g][3], a);
            }
            // 2 product sweeps: (Ah + Al) * B
#pragma unroll
            for (int mi = 0; mi < 4; ++mi)
#pragma unroll
                for (int ni = 0; ni < 8; ++ni)
                    MMA_F16(acc[mi][ni], AHf[mi], Bf[ni>>1][ni&1], Bf[ni>>1][(ni&1)+2]);
#pragma unroll
            for (int mi = 0; mi < 4; ++mi)
#pragma unroll
                for (int ni = 0; ni < 8; ++ni)
                    MMA_F16(acc[mi][ni], ALf[mi], Bf[ni>>1][ni&1], Bf[ni>>1][(ni&1)+2]);
        }
    }

    if (which == 1) {
#pragma unroll
        for (int mi = 0; mi < 4; ++mi) {
            const int row = m0 + wm * 64 + mi * 16 + (lane >> 2);
#pragma unroll
            for (int ni = 0; ni < 8; ++ni) {
                const int col = n0 + wn * 64 + ni * 8 + (lane & 3) * 2;
                float* cp = Cout + (size_t)row * 2048 + col;
                *(float2*)cp = make_float2(acc[mi][ni][0], acc[mi][ni][1]);
                *(float2*)(cp + (size_t)8 * 2048) = make_float2(acc[mi][ni][2], acc[mi][ni][3]);
            }
        }
        return;
    }

    // ---- fused QKV epilogue: stage fp32 tile in smem, then RoPE/fp16/transpose
    CP_WAIT0();
    __syncthreads();
    float* sf = (float*)smem;        // [256][EPI_STR]
#pragma unroll
    for (int mi = 0; mi < 4; ++mi) {
        const int row = wm * 64 + mi * 16 + (lane >> 2);
#pragma unroll
        for (int ni = 0; ni < 8; ++ni) {
            const int col = wn * 64 + ni * 8 + (lane & 3) * 2;
            sf[row * EPI_STR + col]           = acc[mi][ni][0];
            sf[row * EPI_STR + col + 1]       = acc[mi][ni][1];
            sf[(row + 8) * EPI_STR + col]     = acc[mi][ni][2];
            sf[(row + 8) * EPI_STR + col + 1] = acc[mi][ni][3];
        }
    }
    __syncthreads();

    if (n0 >= 2560) {
        // V region: transpose to fp16 vth [b][hk][d][s]
        const int b = m0 >> 11, s0l = m0 & 2047, hk = (n0 - 2560) >> 7;
#pragma unroll
        for (int it = 0; it < 16; ++it) {
            const int d = it * 8 + wid;
            const size_t ob = ((size_t)(b * NKV_ + hk) * HD_ + d) * S_ + s0l;
#pragma unroll
            for (int k = 0; k < 8; ++k) {
                const int s = lane + 32 * k;
                g_vth[ob + s] = __float2half_rn(sf[s * EPI_STR + d]);
            }
        }
    } else {
        // Q or K region: RoPE + fp16 store
        const bool isq = (n0 < 2048);
        __half* dh = isq ? g_qh : g_kh;
        const int rowstr = isq ? 2048 : 512;
        const int coloff = isq ? n0 : (n0 - 2048);
        const int c = 2 * lane;
        for (int r = wid; r < 256; r += 8) {
            const int m = m0 + r, s = m & (S_ - 1);
            float x1a = sf[r * EPI_STR + c],      x1b = sf[r * EPI_STR + c + 1];
            float x2a = sf[r * EPI_STR + c + 64], x2b = sf[r * EPI_STR + c + 65];
            float2 cs = *(const float2*)(g_cos + s * 64 + c);
            float2 sn = *(const float2*)(g_sin + s * 64 + c);
            float y1a = x1a * cs.x - x2a * sn.x;
            float y1b = x1b * cs.y - x2b * sn.y;
            float y2a = x2a * cs.x + x1a * sn.x;
            float y2b = x2b * cs.y + x1b * sn.y;
            size_t base = (size_t)m * rowstr + coloff;
            *(__half2*)(dh + base + c)      = __floats2half2_rn(y1a, y1b);
            *(__half2*)(dh + base + c + 64) = __floats2half2_rn(y2a, y2b);
        }
    }
}

// ---------------- fp16 tensor-core causal flash attention --------------------
// CTA: 128 q-rows, 8 warps x 16 rows. Q hoisted to regs (fp16, 32 regs).
// smem: K ring 2x16K [0,32K) | V ring 2x16K [32K,64K).
#define FLASH_SMEM 65536

__global__ __launch_bounds__(256) void flash_tc()
{
    extern __shared__ char smem[];
    const uint32_t sb = smem_u32(smem);
    const int tid = threadIdx.x;
    const int wid = tid >> 5, lane = tid & 31;
    const int lrow = lane & 15, lchunk = lane >> 4;
    const int qb = (int)gridDim.x - 1 - (int)blockIdx.x;   // big blocks first
    const int h = blockIdx.y, b = blockIdx.z;
    const int hk = h >> 2;
    const int q0 = qb * 128;
    const int wq0 = wid * 16;

    // ---- stage Q (fp16, 32KB), hoist fragments, then release staging area
#pragma unroll
    for (int i = 0; i < 8; ++i) {
        int ch = tid + (i << 8);
        int r = ch >> 4, c16 = ch & 15;
        const __half* src = g_qh + ((size_t)((b * S_ + q0 + r) * NH_ + h)) * HD_ + c16 * 8;
        CP_ASYNC16(sb + (c16 >> 2) * 8192 + sw_off(r, c16 & 3), src);
    }
    CP_COMMIT();
    CP_WAIT0();
    __syncthreads();

    uint32_t QH[8][4];
#pragma unroll
    for (int kk = 0; kk < 8; ++kk) {
        const int p = kk >> 1, cc = ((kk & 1) << 1) + lchunk;
        uint32_t qa = sb + p * 8192 + sw_off(wq0 + lrow, cc);
        LDSM_X4(QH[kk][0], QH[kk][1], QH[kk][2], QH[kk][3], qa);
    }
    __syncthreads();     // Q consumed; KV ring may overwrite

    auto load_kv = [&](int jb, int s) {
        const int j0 = jb * 64;
        const uint32_t kb = sb + s * 16384;
        const uint32_t vb = sb + 32768 + s * 16384;
#pragma unroll
        for (int i = 0; i < 8; ++i) {
            int ch = tid + (i << 8);
            if (ch < 1024) {                 // K: 64 rows x 16 chunks
                int r = ch >> 4, c16 = ch & 15;
                const __half* src = g_kh
                    + ((size_t)((b * S_ + j0 + r) * NKV_ + hk)) * HD_ + c16 * 8;
                CP_ASYNC16(kb + (c16 >> 2) * 4096 + sw_off(r, c16 & 3), src);
            } else {                         // Vt: 128 rows(d) x 8 chunks
                int ch2 = ch - 1024;
                int d = ch2 >> 3, c8 = ch2 & 7;
                const __half* src = g_vth
                    + ((size_t)(b * NKV_ + hk) * HD_ + d) * S_ + j0 + c8 * 8;
                CP_ASYNC16(vb + (c8 >> 2) * 8192 + sw_off(d, c8 & 3), src);
            }
        }
        CP_COMMIT();
    };

    load_kv(0, 0);

    float oacc[16][4];
#pragma unroll
    for (int ob = 0; ob < 16; ++ob)
#pragma unroll
        for (int e = 0; e < 4; ++e) oacc[ob][e] = 0.f;
    float m1 = -INFINITY, m2 = -INFINITY, l1 = 0.f, l2 = 0.f;
    const float scale2 = 0.12751726f;              // log2(e)/sqrt(128)
    const int r1g = q0 + wq0 + (lane >> 2);
    const int njb = 2 * qb + 2;

    for (int jb = 0; jb < njb; ++jb) {
        if (jb + 1 < njb) { load_kv(jb + 1, (jb + 1) & 1); CP_WAIT1(); }
        else              { CP_WAIT0(); }
        __syncthreads();
        const uint32_t kb = sb + (jb & 1) * 16384;
        const uint32_t vb = sb + 32768 + (jb & 1) * 16384;
        const int j0 = jb * 64;

        if (j0 <= q0 + wq0 + 15) {
            // ---- S = Q K^T (fp16 single)
            float sacc[8][4];
#pragma unroll
            for (int nb = 0; nb < 8; ++nb)
#pragma unroll
                for (int e = 0; e < 4; ++e) sacc[nb][e] = 0.f;

#pragma unroll
            for (int kk = 0; kk < 8; ++kk) {
                const int p = kk >> 1, cc = ((kk & 1) << 1) + lchunk;
                uint32_t KH[4][4];
#pragma unroll
                for (int g = 0; g < 4; ++g) {
                    uint32_t ka = kb + p * 4096 + sw_off(g * 16 + lrow, cc);
                    LDSM_X4(KH[g][0], KH[g][1], KH[g][2], KH[g][3], ka);
                }
#pragma unroll
                for (int nb = 0; nb < 8; ++nb)
                    MMA_F16(sacc[nb], QH[kk], KH[nb>>1][nb&1], KH[nb>>1][(nb&1)+2]);
            }

            // ---- online softmax (exp2 domain)
            const bool msk = (j0 + 63 > q0 + wq0);
            float mx1 = -INFINITY, mx2 = -INFINITY;
#pragma unroll
            for (int nb = 0; nb < 8; ++nb) {
                int c0 = j0 + nb * 8 + ((lane & 3) << 1);
                float x0 = sacc[nb][0] * scale2, x1 = sacc[nb][1] * scale2;
                float x2 = sacc[nb][2] * scale2, x3 = sacc[nb][3] * scale2;
                if (msk) {
                    if (c0     > r1g)     x0 = -INFINITY;
                    if (c0 + 1 > r1g)     x1 = -INFINITY;
                    if (c0     > r1g + 8) x2 = -INFINITY;
                    if (c0 + 1 > r1g + 8) x3 = -INFINITY;
                }
                sacc[nb][0] = x0; sacc[nb][1] = x1; sacc[nb][2] = x2; sacc[nb][3] = x3;
                mx1 = fmaxf(mx1, fmaxf(x0, x1));
                mx2 = fmaxf(mx2, fmaxf(x2, x3));
            }
            mx1 = fmaxf(mx1, __shfl_xor_sync(0xffffffffu, mx1, 1));
            mx1 = fmaxf(mx1, __shfl_xor_sync(0xffffffffu, mx1, 2));
            mx2 = fmaxf(mx2, __shfl_xor_sync(0xffffffffu, mx2, 1));
            mx2 = fmaxf(mx2, __shfl_xor_sync(0xffffffffu, mx2, 2));
            float mn1 = fmaxf(m1, mx1), mn2 = fmaxf(m2, mx2);
            float rs1 = 0.f, rs2 = 0.f;
#pragma unroll
            for (int nb = 0; nb < 8; ++nb) {
                float p0 = exp2f(sacc[nb][0] - mn1), p1 = exp2f(sacc[nb][1] - mn1);
                float p2 = exp2f(sacc[nb][2] - mn2), p3 = exp2f(sacc[nb][3] - mn2);
                sacc[nb][0] = p0; sacc[nb][1] = p1; sacc[nb][2] = p2; sacc[nb][3] = p3;
                rs1 += p0 + p1; rs2 += p2 + p3;
            }
            rs1 += __shfl_xor_sync(0xffffffffu, rs1, 1);
            rs1 += __shfl_xor_sync(0xffffffffu, rs1, 2);
            rs2 += __shfl_xor_sync(0xffffffffu, rs2, 1);
            rs2 += __shfl_xor_sync(0xffffffffu, rs2, 2);
            bool nochange = (mn1 == m1) && (mn2 == m2);
            if (!__all_sync(0xffffffffu, nochange)) {
                float cr1 = exp2f(m1 - mn1), cr2 = exp2f(m2 - mn2);
                l1 *= cr1; l2 *= cr2;
#pragma unroll
                for (int ob = 0; ob < 16; ++ob) {
                    oacc[ob][0] *= cr1; oacc[ob][1] *= cr1;
                    oacc[ob][2] *= cr2; oacc[ob][3] *= cr2;
                }
            }
            l1 += rs1; l2 += rs2;
            m1 = mn1; m2 = mn2;

            // ---- O += P V (fp16 single, P packed from registers)
#pragma unroll
            for (int kc = 0; kc < 4; ++kc) {
                uint32_t PH[4];
                PH[0] = pack_h2(sacc[2*kc][0],   sacc[2*kc][1]);
                PH[1] = pack_h2(sacc[2*kc][2],   sacc[2*kc][3]);
                PH[2] = pack_h2(sacc[2*kc+1][0], sacc[2*kc+1][1]);
                PH[3] = pack_h2(sacc[2*kc+1][2], sacc[2*kc+1][3]);
                const int p = kc >> 1, cc = ((kc & 1) << 1) + lchunk;
#pragma unroll
                for (int g = 0; g < 8; ++g) {
                    uint32_t VH[4];
                    uint32_t va = vb + p * 8192 + sw_off(g * 16 + lrow, cc);
                    LDSM_X4(VH[0], VH[1], VH[2], VH[3], va);
                    MMA_F16(oacc[2*g],   PH, VH[0], VH[2]);
                    MMA_F16(oacc[2*g+1], PH, VH[1], VH[3]);
                }
            }
        }
        __syncthreads();
    }

    // ---- epilogue: normalize + fp16 split-write to aoh/aol
    float i1 = 1.f / l1, i2 = 1.f / l2;
    size_t base1 = (size_t)(b * S_ + r1g) * 2048 + h * 128;
    size_t base2 = base1 + (size_t)8 * 2048;
#pragma unroll
    for (int ob = 0; ob < 16; ++ob) {
        int col = ob * 8 + ((lane & 3) << 1);
        store_split2h(g_aoh + base1 + col, g_aol + base1 + col,
                      oacc[ob][0] * i1, oacc[ob][1] * i1);
        store_split2h(g_aoh + base2 + col, g_aol + base2 + col,
                      oacc[ob][2] * i2, oacc[ob][3] * i2);
    }
}

// ---------------- launch ----------------------------------------------------
extern "C" void kernel_launch(void* const* d_in, const int* in_sizes, int n_in,
                              void* d_out, int out_size)
{
    (void)in_sizes; (void)n_in; (void)out_size;
    const float* hs = (const float*)d_in[0];
    const float* Wq = (const float*)d_in[1];
    const float* Wk = (const float*)d_in[2];
    const float* Wv = (const float*)d_in[3];
    const float* Wo = (const float*)d_in[4];
    float* out = (float*)d_out;

    cudaFuncSetAttribute(tc_gemm, cudaFuncAttributeMaxDynamicSharedMemorySize, GEMM_SMEM);
    cudaFuncSetAttribute(flash_tc, cudaFuncAttributeMaxDynamicSharedMemorySize, FLASH_SMEM);

    split_all<<<SPLIT_TOTAL / 4 / 256, 256>>>(hs, Wq, Wk, Wv, Wo);
    rope_table_kernel<<<(S_ * 64 + 255) / 256, 256>>>();
    tc_gemm<<<dim3(24, 16), 256, GEMM_SMEM>>>(0, nullptr);
    flash_tc<<<dim3(S_ / 128, NH_, B_), 256, FLASH_SMEM>>>();
    tc_gemm<<<dim3(16, 16), 256, GEMM_SMEM>>>(1, out);
}